// round 15
// baseline (speedup 1.0000x reference)
#include <cuda_runtime.h>

// Problem constants: N=1024 agents, H=64 hidden.
#define Nn 1024
#define Hh 64
#define EE (Nn * (Nn - 1))   // 1047552 edges

// Factored first layer + relu-elimination scalars:
//   gA[i][k] = b1[k] + sum_c emb[i][c] * W1[c][k]
//   gB[j][k] =         sum_c emb[j][c] * W1[64+c][k]
//   gGamma[i] = b2 + 0.5 * <W2, gA[i]>,   gDelta[j] = 0.5 * <W2, gB[j]>
__device__ float gA[Nn * Hh];
__device__ float gB[Nn * Hh];
__device__ float gGamma[Nn];
__device__ float gDelta[Nn];

// ---------------------------------------------------------------------------
// Kernel 1: gA/gB = emb @ [W1_top | W1_bot], L1-DIRECT (no SMEM staging):
// W1 is 32 KB and fits in L1; all 8 warps of a CTA share the same lines, so
// after warm-up every W1 read is an L1 hit. This removes the 16-LDG front
// batch, both __syncthreads, and all staging LDS traffic that made the
// staged version latency-bound on its 0.86-wave grid.
// 128 CTAs x 256 threads; warp = one emb row, lanes cover the 128 output
// cols in float4 quads. Plus gGamma/gDelta via in-warp butterfly reduce.
// ---------------------------------------------------------------------------
__global__ void __launch_bounds__(256) prep_kernel(const float* __restrict__ emb,
                                                   const float* __restrict__ W1,
                                                   const float* __restrict__ b1,
                                                   const float* __restrict__ W2,
                                                   const float* __restrict__ b2ptr) {
    const int t = threadIdx.x;
    const int row = blockIdx.x * 8 + (t >> 5);
    const int lane = t & 31;
    const int m = lane * 4;
    const int half = m >> 6;
    const int k = m & 63;
    const float* w1base = W1 + half * Hh * Hh;

    float acc0 = 0.f, acc1 = 0.f, acc2 = 0.f, acc3 = 0.f;
#pragma unroll
    for (int c = 0; c < Hh; c += 4) {
        const float4 e4 = *reinterpret_cast<const float4*>(emb + row * Hh + c);
        const float4 w0 = *reinterpret_cast<const float4*>(w1base + (c + 0) * Hh + k);
        const float4 w1v = *reinterpret_cast<const float4*>(w1base + (c + 1) * Hh + k);
        const float4 w2v = *reinterpret_cast<const float4*>(w1base + (c + 2) * Hh + k);
        const float4 w3v = *reinterpret_cast<const float4*>(w1base + (c + 3) * Hh + k);
        acc0 = fmaf(e4.x, w0.x, acc0); acc0 = fmaf(e4.y, w1v.x, acc0);
        acc0 = fmaf(e4.z, w2v.x, acc0); acc0 = fmaf(e4.w, w3v.x, acc0);
        acc1 = fmaf(e4.x, w0.y, acc1); acc1 = fmaf(e4.y, w1v.y, acc1);
        acc1 = fmaf(e4.z, w2v.y, acc1); acc1 = fmaf(e4.w, w3v.y, acc1);
        acc2 = fmaf(e4.x, w0.z, acc2); acc2 = fmaf(e4.y, w1v.z, acc2);
        acc2 = fmaf(e4.z, w2v.z, acc2); acc2 = fmaf(e4.w, w3v.z, acc2);
        acc3 = fmaf(e4.x, w0.w, acc3); acc3 = fmaf(e4.y, w1v.w, acc3);
        acc3 = fmaf(e4.z, w2v.w, acc3); acc3 = fmaf(e4.w, w3v.w, acc3);
    }

    float4 o;
    if (half == 0) {
        const float4 bb = *reinterpret_cast<const float4*>(b1 + k);
        o.x = acc0 + bb.x; o.y = acc1 + bb.y; o.z = acc2 + bb.z; o.w = acc3 + bb.w;
        *reinterpret_cast<float4*>(&gA[row * Hh + k]) = o;
    } else {
        o.x = acc0; o.y = acc1; o.z = acc2; o.w = acc3;
        *reinterpret_cast<float4*>(&gB[row * Hh + k]) = o;
    }

    const float4 wv = *reinterpret_cast<const float4*>(W2 + k);
    float part = o.x * wv.x + o.y * wv.y + o.z * wv.z + o.w * wv.w;
#pragma unroll
    for (int off = 8; off > 0; off >>= 1)
        part += __shfl_xor_sync(0xffffffffu, part, off);
    if (lane == 0)  gGamma[row] = b2ptr[0] + 0.5f * part;
    if (lane == 16) gDelta[row] = 0.5f * part;
}

// ---------------------------------------------------------------------------
// Kernel 2 (unchanged from round 14 — measured at its ~12.7us floor):
// per-pair MLP, relu eliminated, all-scalar inner math:
//   x(i,j) = gGamma[i] + gDelta[j] + sum_k (W2[k]/2) * |A_ik + B_jk|
// Grid 32x32 = 1024 CTAs, 64 threads, 4x4 micro-tile (16 pairs/thread).
// Bank analysis (TPAD=76, quad = 12*row mod 32): rows r+8u walk 8 distinct
// quads; A rows broadcast per 8-lane phase -> all LDS.128 conflict-free.
// Sigmoid: __expf + __fdividef. __launch_bounds__(64,11).
// ---------------------------------------------------------------------------
#define TSI 32
#define TSJ 32
#define TPAD 76

__global__ void __launch_bounds__(64, 11) pair_kernel(const float* __restrict__ W2,
                                                      float* __restrict__ out) {
    __shared__ float sA[TSI * TPAD];
    __shared__ float sB[TSJ * TPAD];
    __shared__ float sW2[64];    // pre-scaled by 0.5
    __shared__ float sGam[TSI];
    __shared__ float sDel[TSJ];

    const int t = threadIdx.x;
    const int tx = t & 7;
    const int ty = t >> 3;
    const int i0 = blockIdx.y * TSI;
    const int j0 = blockIdx.x * TSJ;

#pragma unroll
    for (int q = t; q < 1024; q += 64) {
        if (q < 512) {
            const int r = q >> 4, c4 = (q & 15) * 4;
            *reinterpret_cast<float4*>(&sA[r * TPAD + c4]) =
                *reinterpret_cast<const float4*>(&gA[(i0 + r) * Hh + c4]);
        } else {
            const int q2 = q - 512;
            const int r = q2 >> 4, c4 = (q2 & 15) * 4;
            *reinterpret_cast<float4*>(&sB[r * TPAD + c4]) =
                *reinterpret_cast<const float4*>(&gB[(j0 + r) * Hh + c4]);
        }
    }
    sW2[t] = 0.5f * W2[t];
    if (t < 32) sGam[t] = gGamma[i0 + t];
    else        sDel[t - 32] = gDelta[j0 + (t - 32)];
    __syncthreads();

    float acc[4][4] = {};

    const float* aBase = &sA[ty * TPAD];
    const float* bBase = &sB[tx * TPAD];

#pragma unroll
    for (int k = 0; k < Hh; k += 4) {
        const float4 wq = *reinterpret_cast<const float4*>(&sW2[k]);
        float4 av[4], bv[4];
#pragma unroll
        for (int u = 0; u < 4; u++)
            av[u] = *reinterpret_cast<const float4*>(aBase + (8 * u) * TPAD + k);
#pragma unroll
        for (int u = 0; u < 4; u++)
            bv[u] = *reinterpret_cast<const float4*>(bBase + (8 * u) * TPAD + k);

#pragma unroll
        for (int ii = 0; ii < 4; ii++) {
#pragma unroll
            for (int jj = 0; jj < 4; jj++) {
                float a = acc[ii][jj];
                a = fmaf(fabsf(av[ii].x + bv[jj].x), wq.x, a);
                a = fmaf(fabsf(av[ii].y + bv[jj].y), wq.y, a);
                a = fmaf(fabsf(av[ii].z + bv[jj].z), wq.z, a);
                a = fmaf(fabsf(av[ii].w + bv[jj].w), wq.w, a);
                acc[ii][jj] = a;
            }
        }
    }

#pragma unroll
    for (int ii = 0; ii < 4; ii++) {
        const int i = i0 + ty + 8 * ii;
        const float gi = sGam[ty + 8 * ii];
#pragma unroll
        for (int jj = 0; jj < 4; jj++) {
            const int j = j0 + tx + 8 * jj;
            if (j == i) continue;
            const int e = i * (Nn - 1) + j - (j > i ? 1 : 0);
            const float x = acc[ii][jj] + gi + sDel[tx + 8 * jj];
            const float ex = __expf(-x);
            out[e] = (float)i;
            out[EE + e] = (float)j;
            out[2 * EE + e] = __fdividef(1.0f, 1.0f + ex);
        }
    }
}

extern "C" void kernel_launch(void* const* d_in, const int* in_sizes, int n_in,
                              void* d_out, int out_size) {
    const float* emb = (const float*)d_in[0];  // [1024, 64]
    const float* W1  = (const float*)d_in[1];  // [128, 64]
    const float* b1  = (const float*)d_in[2];  // [64]
    const float* W2  = (const float*)d_in[3];  // [64, 1]
    const float* b2  = (const float*)d_in[4];  // [1]
    float* out = (float*)d_out;

    prep_kernel<<<128, 256>>>(emb, W1, b1, W2, b2);
    pair_kernel<<<dim3(32, 32), 64>>>(W2, out);
}

// round 16
// speedup vs baseline: 1.1193x; 1.1193x over previous
#include <cuda_runtime.h>

// Problem constants: N=1024 agents, H=64 hidden.
#define Nn 1024
#define Hh 64
#define EE (Nn * (Nn - 1))   // 1047552 edges

// Factored first layer + relu-elimination scalars:
//   gA[i][k] = b1[k] + sum_c emb[i][c] * W1[c][k]
//   gB[j][k] =         sum_c emb[j][c] * W1[64+c][k]
//   gGamma[i] = b2 + 0.5 * <W2, gA[i]>,   gDelta[j] = 0.5 * <W2, gB[j]>
__device__ float gA[Nn * Hh];
__device__ float gB[Nn * Hh];
__device__ float gGamma[Nn];
__device__ float gDelta[Nn];

// ---------------------------------------------------------------------------
// Kernel 1: HALF-STAGED prep. 256 CTAs x 256 threads, ALL resident (one
// wave, ~14 warps/SM vs 7 before). CTA c: half = c&1 (0 -> gA / top half of
// W1, 1 -> gB / bottom half), rows (c>>1)*8 .. +7, warp = one row.
// Stage only the needed 16 KB half of W1 (4 LDG.128/thread front batch,
// quarter of the old burst). Lane owns output cols {2l, 2l+1}:
//   per c: one conflict-free LDS.64 of the 256B W1 row + 2 FFMA into two
//   independent accumulator chains; emb read as broadcast LDG.128 per 4 c.
// gamma/delta via in-warp dot + 5-shuffle butterfly.
// ---------------------------------------------------------------------------
__global__ void __launch_bounds__(256) prep_kernel(const float* __restrict__ emb,
                                                   const float* __restrict__ W1,
                                                   const float* __restrict__ b1,
                                                   const float* __restrict__ W2,
                                                   const float* __restrict__ b2ptr) {
    __shared__ float sW1h[64 * 64];   // 16 KB: one half of W1

    const int t = threadIdx.x;
    const int c = blockIdx.x;
    const int half = c & 1;
    const float* w1h = W1 + half * Hh * Hh;

    // Stage this half: 1024 float4 / 256 threads = 4 each (coalesced).
#pragma unroll
    for (int q = t; q < 1024; q += 256)
        reinterpret_cast<float4*>(sW1h)[q] = reinterpret_cast<const float4*>(w1h)[q];
    __syncthreads();

    const int wid = t >> 5;
    const int lane = t & 31;
    const int row = (c >> 1) * 8 + wid;
    const int k = 2 * lane;           // two output cols per lane

    float acc0 = 0.f, acc1 = 0.f;
    const float* embRow = emb + row * Hh;
#pragma unroll
    for (int cc = 0; cc < Hh; cc += 4) {
        const float4 e4 = *reinterpret_cast<const float4*>(embRow + cc);  // broadcast
        const float2 w0 = *reinterpret_cast<const float2*>(&sW1h[(cc + 0) * Hh + k]);
        const float2 w1v = *reinterpret_cast<const float2*>(&sW1h[(cc + 1) * Hh + k]);
        const float2 w2v = *reinterpret_cast<const float2*>(&sW1h[(cc + 2) * Hh + k]);
        const float2 w3v = *reinterpret_cast<const float2*>(&sW1h[(cc + 3) * Hh + k]);
        acc0 = fmaf(e4.x, w0.x, acc0); acc1 = fmaf(e4.x, w0.y, acc1);
        acc0 = fmaf(e4.y, w1v.x, acc0); acc1 = fmaf(e4.y, w1v.y, acc1);
        acc0 = fmaf(e4.z, w2v.x, acc0); acc1 = fmaf(e4.z, w2v.y, acc1);
        acc0 = fmaf(e4.w, w3v.x, acc0); acc1 = fmaf(e4.w, w3v.y, acc1);
    }

    float2 o;
    if (half == 0) {
        const float2 bb = *reinterpret_cast<const float2*>(b1 + k);
        o.x = acc0 + bb.x; o.y = acc1 + bb.y;
        *reinterpret_cast<float2*>(&gA[row * Hh + k]) = o;
    } else {
        o.x = acc0; o.y = acc1;
        *reinterpret_cast<float2*>(&gB[row * Hh + k]) = o;
    }

    // gamma/delta: dot lane's 2 outputs with W2, butterfly over the warp.
    const float2 wv = *reinterpret_cast<const float2*>(W2 + k);
    float part = o.x * wv.x + o.y * wv.y;
#pragma unroll
    for (int off = 16; off > 0; off >>= 1)
        part += __shfl_xor_sync(0xffffffffu, part, off);
    if (lane == 0) {
        if (half == 0) gGamma[row] = b2ptr[0] + 0.5f * part;
        else           gDelta[row] = 0.5f * part;
    }
}

// ---------------------------------------------------------------------------
// Kernel 2 (byte-identical to round 14 — measured at its ~12.7us floor):
// per-pair MLP, relu eliminated, all-scalar inner math:
//   x(i,j) = gGamma[i] + gDelta[j] + sum_k (W2[k]/2) * |A_ik + B_jk|
// Grid 32x32 = 1024 CTAs, 64 threads, 4x4 micro-tile (16 pairs/thread).
// Bank analysis (TPAD=76, quad = 12*row mod 32): rows r+8u walk 8 distinct
// quads; A rows broadcast per 8-lane phase -> all LDS.128 conflict-free.
// Sigmoid: __expf + __fdividef. __launch_bounds__(64,11).
// ---------------------------------------------------------------------------
#define TSI 32
#define TSJ 32
#define TPAD 76

__global__ void __launch_bounds__(64, 11) pair_kernel(const float* __restrict__ W2,
                                                      float* __restrict__ out) {
    __shared__ float sA[TSI * TPAD];
    __shared__ float sB[TSJ * TPAD];
    __shared__ float sW2[64];    // pre-scaled by 0.5
    __shared__ float sGam[TSI];
    __shared__ float sDel[TSJ];

    const int t = threadIdx.x;
    const int tx = t & 7;
    const int ty = t >> 3;
    const int i0 = blockIdx.y * TSI;
    const int j0 = blockIdx.x * TSJ;

#pragma unroll
    for (int q = t; q < 1024; q += 64) {
        if (q < 512) {
            const int r = q >> 4, c4 = (q & 15) * 4;
            *reinterpret_cast<float4*>(&sA[r * TPAD + c4]) =
                *reinterpret_cast<const float4*>(&gA[(i0 + r) * Hh + c4]);
        } else {
            const int q2 = q - 512;
            const int r = q2 >> 4, c4 = (q2 & 15) * 4;
            *reinterpret_cast<float4*>(&sB[r * TPAD + c4]) =
                *reinterpret_cast<const float4*>(&gB[(j0 + r) * Hh + c4]);
        }
    }
    sW2[t] = 0.5f * W2[t];
    if (t < 32) sGam[t] = gGamma[i0 + t];
    else        sDel[t - 32] = gDelta[j0 + (t - 32)];
    __syncthreads();

    float acc[4][4] = {};

    const float* aBase = &sA[ty * TPAD];
    const float* bBase = &sB[tx * TPAD];

#pragma unroll
    for (int k = 0; k < Hh; k += 4) {
        const float4 wq = *reinterpret_cast<const float4*>(&sW2[k]);
        float4 av[4], bv[4];
#pragma unroll
        for (int u = 0; u < 4; u++)
            av[u] = *reinterpret_cast<const float4*>(aBase + (8 * u) * TPAD + k);
#pragma unroll
        for (int u = 0; u < 4; u++)
            bv[u] = *reinterpret_cast<const float4*>(bBase + (8 * u) * TPAD + k);

#pragma unroll
        for (int ii = 0; ii < 4; ii++) {
#pragma unroll
            for (int jj = 0; jj < 4; jj++) {
                float a = acc[ii][jj];
                a = fmaf(fabsf(av[ii].x + bv[jj].x), wq.x, a);
                a = fmaf(fabsf(av[ii].y + bv[jj].y), wq.y, a);
                a = fmaf(fabsf(av[ii].z + bv[jj].z), wq.z, a);
                a = fmaf(fabsf(av[ii].w + bv[jj].w), wq.w, a);
                acc[ii][jj] = a;
            }
        }
    }

#pragma unroll
    for (int ii = 0; ii < 4; ii++) {
        const int i = i0 + ty + 8 * ii;
        const float gi = sGam[ty + 8 * ii];
#pragma unroll
        for (int jj = 0; jj < 4; jj++) {
            const int j = j0 + tx + 8 * jj;
            if (j == i) continue;
            const int e = i * (Nn - 1) + j - (j > i ? 1 : 0);
            const float x = acc[ii][jj] + gi + sDel[tx + 8 * jj];
            const float ex = __expf(-x);
            out[e] = (float)i;
            out[EE + e] = (float)j;
            out[2 * EE + e] = __fdividef(1.0f, 1.0f + ex);
        }
    }
}

extern "C" void kernel_launch(void* const* d_in, const int* in_sizes, int n_in,
                              void* d_out, int out_size) {
    const float* emb = (const float*)d_in[0];  // [1024, 64]
    const float* W1  = (const float*)d_in[1];  // [128, 64]
    const float* b1  = (const float*)d_in[2];  // [64]
    const float* W2  = (const float*)d_in[3];  // [64, 1]
    const float* b2  = (const float*)d_in[4];  // [1]
    float* out = (float*)d_out;

    prep_kernel<<<256, 256>>>(emb, W1, b1, W2, b2);
    pair_kernel<<<dim3(32, 32), 64>>>(W2, out);
}